// round 10
// baseline (speedup 1.0000x reference)
#include <cuda_runtime.h>
#include <cstdint>
#include <math.h>

#define Bb 16
#define Nn 128
#define DZ 128
#define DS 256
#define Hh 8
#define HDIM 32
#define BI (Bb*Nn)
#define INV_SCALE 0.17677669529663687f
#define LN_EPS 1e-5f
#define ZP 132

// ---------------- scratch ----------------
__device__ __align__(16) float g_SN  [BI*DS];
__device__ __align__(16) float g_QKG [BI*Hh*DZ];
__device__ __align__(16) float g_CTX [BI*Hh*DZ];
__device__ __align__(16) float g_OUTS[BI*DS];
__device__ __align__(16) float g_W3  [Hh*DZ*DS];   // [o=h*128+d][c]
__device__ __align__(16) float g_c3  [Hh*DZ];
__device__ __align__(16) float g_W4T [Hh*DS];      // [h][c]
__device__ __align__(16) float g_cq0 [Hh];

__device__ __forceinline__ unsigned f2tf(float x) {
    unsigned r; asm("cvt.rna.tf32.f32 %0, %1;" : "=r"(r) : "f"(x)); return r;
}
__device__ __forceinline__ uint4 tf4(float4 v) {
    return make_uint4(f2tf(v.x), f2tf(v.y), f2tf(v.z), f2tf(v.w));
}
__device__ __forceinline__ void mma_tf32(float* c, const unsigned* a, unsigned b0, unsigned b1) {
    asm volatile(
        "mma.sync.aligned.m16n8k8.row.col.f32.tf32.tf32.f32 "
        "{%0,%1,%2,%3}, {%4,%5,%6,%7}, {%8,%9}, {%0,%1,%2,%3};"
        : "+f"(c[0]), "+f"(c[1]), "+f"(c[2]), "+f"(c[3])
        : "r"(a[0]), "r"(a[1]), "r"(a[2]), "r"(a[3]), "r"(b0), "r"(b1));
}
__device__ __forceinline__ void cp16(unsigned int dst, const void* src) {
    asm volatile("cp.async.cg.shared.global [%0], [%1], 16;\n" :: "r"(dst), "l"(src));
}

// ---------------- fused pre: s_query LN (BI blocks) + W4T/cq0 (1 block) + W3/c3 (128 blocks) ----------------
__global__ void pre_kernel(const float* __restrict__ s, const float* __restrict__ gs,
                           const float* __restrict__ bs,
                           const float* __restrict__ wk, const float* __restrict__ bk,
                           const float* __restrict__ bz, const float* __restrict__ gz,
                           const float* __restrict__ wq, const float* __restrict__ bq) {
    __shared__ float sh[288];
    int t = threadIdx.x;
    int blk = blockIdx.x;
    int w = t >> 5, l = t & 31;

    if (blk < BI) {
        // layernorm of s_query
        int bi = blk;
        float x = s[(size_t)bi*DS + t];
        float sm = x, sq = x*x;
        #pragma unroll
        for (int o = 16; o > 0; o >>= 1) {
            sm += __shfl_xor_sync(0xffffffffu, sm, o);
            sq += __shfl_xor_sync(0xffffffffu, sq, o);
        }
        float* ps = sh; float* pq = sh + 8; float* mv = sh + 16;
        if (l == 0) { ps[w] = sm; pq[w] = sq; }
        __syncthreads();
        if (t == 0) {
            float a = 0.f, b2 = 0.f;
            #pragma unroll
            for (int k = 0; k < 8; k++) { a += ps[k]; b2 += pq[k]; }
            float m = a * (1.0f/DS);
            mv[0] = m;
            mv[1] = rsqrtf(b2 * (1.0f/DS) - m*m + LN_EPS);
        }
        __syncthreads();
        g_SN[(size_t)bi*DS + t] = (x - mv[0]) * mv[1] * gs[t] + bs[t];
    } else if (blk == BI) {
        // wkb (local) -> W4T, cq0
        float* swkb = sh;
        for (int r = w; r < DS; r += 8) {
            float a = 0.f;
            #pragma unroll
            for (int k = 0; k < 4; k++) { int dd = l + 32*k; a += wk[(size_t)r*DZ + dd] * bz[dd]; }
            #pragma unroll
            for (int oo = 16; oo > 0; oo >>= 1) a += __shfl_xor_sync(0xffffffffu, a, oo);
            if (l == 0) swkb[r] = a + bk[r];
        }
        __syncthreads();
        #pragma unroll
        for (int h = 0; h < Hh; h++) {
            float a = 0.f;
            #pragma unroll
            for (int e = 0; e < HDIM; e++)
                a += wq[(size_t)(h*HDIM+e)*DS + t] * swkb[h*HDIM+e];
            g_W4T[h*DS + t] = a * INV_SCALE;
        }
        if (t < Hh) {
            float a = 0.f;
            for (int e = 0; e < HDIM; e++) a += bq[t*HDIM+e] * swkb[t*HDIM+e];
            g_cq0[t] = a * INV_SCALE;
        }
    } else {
        // W3/c3: block handles head h, 8 d-rows
        int pb = blk - BI - 1;                 // 0..127
        int h = pb >> 4, d0 = (pb & 15) * 8;
        float* swk = sh;                       // [32][8]
        {
            int e = t >> 3, dd = t & 7;
            swk[e*8 + dd] = wk[(size_t)(h*HDIM+e)*DZ + d0 + dd];
        }
        __syncthreads();
        float acc[8];
        #pragma unroll
        for (int dd = 0; dd < 8; dd++) acc[dd] = 0.f;
        #pragma unroll 4
        for (int e = 0; e < HDIM; e++) {
            float wqv = wq[(size_t)(h*HDIM+e)*DS + t];
            #pragma unroll
            for (int dd = 0; dd < 8; dd++) acc[dd] += swk[e*8 + dd] * wqv;
        }
        #pragma unroll
        for (int dd = 0; dd < 8; dd++) {
            int d = d0 + dd;
            g_W3[(size_t)(h*DZ + d)*DS + t] = acc[dd] * gz[d] * INV_SCALE;
        }
        if (t < 8) {
            int d = d0 + t;
            float a = 0.f;
            for (int e = 0; e < HDIM; e++) a += swk[e*8 + t] * bq[h*HDIM+e];
            g_c3[h*DZ + d] = a * gz[d] * INV_SCALE;
        }
    }
}

// ---------------- tf32 GEMM ----------------
template<int BM, int BN, int WGM, int WGN>
__global__ __launch_bounds__(256) void gemm_tc(
        const float* __restrict__ A, int lda,
        const float* __restrict__ B, int ldb,
        const float* __restrict__ bias,
        float* __restrict__ C, int ldc, int K,
        int head_cols, int ahs) {
    constexpr int TM = BM/WGM, TN = BN/WGN, MF = TM/16, NF = TN/8;
    constexpr int LA = BM*8/256;
    constexpr int LB = BN*8/256;
    extern __shared__ float smem[];
    float* Asb = smem;
    float* Bsb = smem + 2*BM*36;

    int t = threadIdx.x, w = t >> 5, lane = t & 31;
    int gr = lane >> 2, gc = lane & 3;
    int wm = (w / WGN) * TM, wn = (w % WGN) * TN;
    int r0 = blockIdx.y * BM, c0 = blockIdx.x * BN;
    int abase = (c0 / head_cols) * ahs;

    float acc[MF][NF][4];
    #pragma unroll
    for (int mf = 0; mf < MF; mf++)
        #pragma unroll
        for (int nf = 0; nf < NF; nf++)
            #pragma unroll
            for (int q = 0; q < 4; q++) acc[mf][nf][q] = 0.f;

    float4 ra[LA], rb[LB];
    #pragma unroll
    for (int i = 0; i < LA; i++) {
        int idx = t + i*256; int row = idx >> 3, k4 = idx & 7;
        ra[i] = *reinterpret_cast<const float4*>(&A[(size_t)(r0+row)*lda + abase + k4*4]);
    }
    #pragma unroll
    for (int i = 0; i < LB; i++) {
        int idx = t + i*256; int row = idx >> 3, k4 = idx & 7;
        rb[i] = *reinterpret_cast<const float4*>(&B[(size_t)(c0+row)*ldb + k4*4]);
    }
    #pragma unroll
    for (int i = 0; i < LA; i++) {
        int idx = t + i*256; int row = idx >> 3, k4 = idx & 7;
        *reinterpret_cast<uint4*>(&Asb[row*36 + k4*4]) = tf4(ra[i]);
    }
    #pragma unroll
    for (int i = 0; i < LB; i++) {
        int idx = t + i*256; int row = idx >> 3, k4 = idx & 7;
        *reinterpret_cast<uint4*>(&Bsb[row*36 + k4*4]) = tf4(rb[i]);
    }
    __syncthreads();

    int nch = K >> 5;
    for (int ch = 0; ch < nch; ch++) {
        int cur = ch & 1;
        const float* As = Asb + cur*BM*36;
        const float* Bs = Bsb + cur*BN*36;
        if (ch + 1 < nch) {
            int kc = (ch+1)*32;
            #pragma unroll
            for (int i = 0; i < LA; i++) {
                int idx = t + i*256; int row = idx >> 3, k4 = idx & 7;
                ra[i] = *reinterpret_cast<const float4*>(&A[(size_t)(r0+row)*lda + abase + kc + k4*4]);
            }
            #pragma unroll
            for (int i = 0; i < LB; i++) {
                int idx = t + i*256; int row = idx >> 3, k4 = idx & 7;
                rb[i] = *reinterpret_cast<const float4*>(&B[(size_t)(c0+row)*ldb + kc + k4*4]);
            }
        }
        #pragma unroll
        for (int ks = 0; ks < 4; ks++) {
            int ko = ks * 8;
            unsigned af[MF][4];
            #pragma unroll
            for (int mf = 0; mf < MF; mf++) {
                const float* ap = &As[(wm + mf*16 + gr)*36 + ko + gc];
                af[mf][0] = __float_as_uint(ap[0]);
                af[mf][1] = __float_as_uint(ap[8*36]);
                af[mf][2] = __float_as_uint(ap[4]);
                af[mf][3] = __float_as_uint(ap[8*36 + 4]);
            }
            #pragma unroll
            for (int nf = 0; nf < NF; nf++) {
                const float* bp = &Bs[(wn + nf*8 + gr)*36 + ko + gc];
                unsigned b0 = __float_as_uint(bp[0]), b1 = __float_as_uint(bp[4]);
                #pragma unroll
                for (int mf = 0; mf < MF; mf++)
                    mma_tf32(acc[mf][nf], af[mf], b0, b1);
            }
        }
        if (ch + 1 < nch) {
            int nxt = cur ^ 1;
            float* Asn = Asb + nxt*BM*36;
            float* Bsn = Bsb + nxt*BN*36;
            #pragma unroll
            for (int i = 0; i < LA; i++) {
                int idx = t + i*256; int row = idx >> 3, k4 = idx & 7;
                *reinterpret_cast<uint4*>(&Asn[row*36 + k4*4]) = tf4(ra[i]);
            }
            #pragma unroll
            for (int i = 0; i < LB; i++) {
                int idx = t + i*256; int row = idx >> 3, k4 = idx & 7;
                *reinterpret_cast<uint4*>(&Bsn[row*36 + k4*4]) = tf4(rb[i]);
            }
            __syncthreads();
        }
    }

    #pragma unroll
    for (int mf = 0; mf < MF; mf++) {
        #pragma unroll
        for (int nf = 0; nf < NF; nf++) {
            int row = r0 + wm + mf*16 + gr;
            int col = c0 + wn + nf*8 + 2*gc;
            float bx = 0.f, by = 0.f;
            if (bias) { bx = bias[col]; by = bias[col+1]; }
            float2 v0 = make_float2(acc[mf][nf][0] + bx, acc[mf][nf][1] + by);
            float2 v1 = make_float2(acc[mf][nf][2] + bx, acc[mf][nf][3] + by);
            *reinterpret_cast<float2*>(&C[(size_t)row*ldc + col])     = v0;
            *reinterpret_cast<float2*>(&C[(size_t)(row+8)*ldc + col]) = v1;
        }
    }
}

// ---------------- fused edge-LN + attention (warp-private z rows, 3 CTA/SM) ----------------
// smem: zt[128*132] qa[8*132] sc[8*132] mj[128] rj[128] Ah[8] cqh[8] sh[8]  = 19288 floats
#define ATTN_SMEM_FLOATS (128*ZP + 2*8*132 + 2*128 + 24)

__global__ __launch_bounds__(256) void attn_kernel(
        const float* __restrict__ z, const int* __restrict__ mask,
        const float* __restrict__ gz, const float* __restrict__ bz) {
    extern __shared__ float smem[];
    float* zt  = smem;                 // raw fp32 z tile
    float* qa  = zt  + 128*ZP;         // tf32 qkg
    float* sc  = qa  + 8*132;          // scores -> tf32 weights
    float* mj  = sc  + 8*132;
    float* rj  = mj  + 128;
    float* Ah  = rj  + 128;
    float* cqh = Ah  + 8;
    float* sh  = cqh + 8;

    int bi = blockIdx.x, b = bi >> 7;
    int t = threadIdx.x, w = t >> 5, l = t & 31;
    int gr = l >> 2, gc = l & 3;
    int j0 = w * 16;

    // 1) warp-private z copies: warp w copies rows [16w, 16w+16)
    {
        unsigned int zt_base = (unsigned int)__cvta_generic_to_shared(zt);
        const float* zb = z + (size_t)bi * 16384;
        #pragma unroll
        for (int k = 0; k < 16; k++) {
            int row = j0 + k;
            cp16(zt_base + (unsigned int)((row*ZP + l*4)*4), zb + row*128 + l*4);
        }
        asm volatile("cp.async.commit_group;\n");
    }

    // 2) overlap: qa (tf32) + Ah; cq from SN . W4T
    {
        float4 v = *reinterpret_cast<const float4*>(&g_QKG[(size_t)bi*1024 + w*128 + l*4]);
        uint4 tv = tf4(v);
        *reinterpret_cast<uint4*>(&qa[w*132 + l*4]) = tv;
        float s = __uint_as_float(tv.x) + __uint_as_float(tv.y)
                + __uint_as_float(tv.z) + __uint_as_float(tv.w);
        #pragma unroll
        for (int o = 16; o > 0; o >>= 1) s += __shfl_xor_sync(0xffffffffu, s, o);
        if (l == 0) Ah[w] = s;
    }
    {
        const float* snp = &g_SN[(size_t)bi*DS];
        const float* w4p = &g_W4T[w*DS];
        float a = 0.f;
        #pragma unroll
        for (int k = 0; k < 8; k++) {
            int c = l + 32*k;
            a += snp[c] * w4p[c];
        }
        #pragma unroll
        for (int o = 16; o > 0; o >>= 1) a += __shfl_xor_sync(0xffffffffu, a, o);
        if (l == 0) cqh[w] = a + g_cq0[w];
    }
    __syncthreads();   // publish qa/Ah/cqh

    // 3) wait own z rows only (warp-local)
    asm volatile("cp.async.wait_group 0;\n");
    __syncwarp();

    // 4) LN stats for own rows: lane pair per row
    {
        int jr = j0 + (l >> 1);
        const float* rp = &zt[jr*ZP + (l & 1)*64];
        float s = 0.f, sq = 0.f;
        #pragma unroll
        for (int k = 0; k < 16; k++) {
            float4 v = *reinterpret_cast<const float4*>(rp + 4*k);
            s  += v.x + v.y + v.z + v.w;
            sq += v.x*v.x + v.y*v.y + v.z*v.z + v.w*v.w;
        }
        s  += __shfl_xor_sync(0xffffffffu, s,  1);
        sq += __shfl_xor_sync(0xffffffffu, sq, 1);
        if ((l & 1) == 0) {
            float m = s * (1.0f/128.0f);
            mj[jr] = m;
            rj[jr] = rsqrtf(sq * (1.0f/128.0f) - m*m + LN_EPS);
        }
    }
    __syncwarp();

    // 5) scores MMA for own rows
    {
        float acc[4] = {0.f, 0.f, 0.f, 0.f};
        unsigned af[4];
        #pragma unroll
        for (int ks = 0; ks < 16; ks++) {
            int ko = ks * 8;
            af[0] = f2tf(zt[(j0+gr)*ZP   + ko + gc]);
            af[1] = f2tf(zt[(j0+gr+8)*ZP + ko + gc]);
            af[2] = f2tf(zt[(j0+gr)*ZP   + ko + gc + 4]);
            af[3] = f2tf(zt[(j0+gr+8)*ZP + ko + gc + 4]);
            unsigned b0 = __float_as_uint(qa[gr*132 + ko + gc]);
            unsigned b1 = __float_as_uint(qa[gr*132 + ko + gc + 4]);
            mma_tf32(acc, af, b0, b1);
        }
        int jA = j0 + gr, jB = j0 + gr + 8;
        int h0 = 2*gc, h1 = 2*gc + 1;
        const int* mrow = &mask[b*128];
        float aA = (mrow[jA] != 0) ? 0.f : -3.0e38f;
        float aB = (mrow[jB] != 0) ? 0.f : -3.0e38f;
        float rA = rj[jA], mA = mj[jA];
        float rB = rj[jB], mB = mj[jB];
        float A0 = Ah[h0], A1 = Ah[h1], C0 = cqh[h0], C1 = cqh[h1];
        sc[h0*132 + jA] = rA*(acc[0] - mA*A0) + C0 + aA;
        sc[h1*132 + jA] = rA*(acc[1] - mA*A1) + C1 + aA;
        sc[h0*132 + jB] = rB*(acc[2] - mB*A0) + C0 + aB;
        sc[h1*132 + jB] = rB*(acc[3] - mB*A1) + C1 + aB;
    }
    __syncthreads();

    // 6) softmax per head; sc becomes aw = attn*r (tf32); sh[h] = sum_j aw*m
    {
        int h = w;
        float v0 = sc[h*132 + l],      v1 = sc[h*132 + l + 32];
        float v2 = sc[h*132 + l + 64], v3 = sc[h*132 + l + 96];
        float mx = fmaxf(fmaxf(v0, v1), fmaxf(v2, v3));
        #pragma unroll
        for (int o = 16; o > 0; o >>= 1) mx = fmaxf(mx, __shfl_xor_sync(0xffffffffu, mx, o));
        float e0 = expf(v0-mx), e1 = expf(v1-mx), e2 = expf(v2-mx), e3 = expf(v3-mx);
        float s = e0+e1+e2+e3;
        #pragma unroll
        for (int o = 16; o > 0; o >>= 1) s += __shfl_xor_sync(0xffffffffu, s, o);
        float inv = 1.0f / s;
        float w0 = e0*inv*rj[l],    w1 = e1*inv*rj[l+32];
        float w2 = e2*inv*rj[l+64], w3 = e3*inv*rj[l+96];
        sc[h*132 + l]      = __uint_as_float(f2tf(w0));
        sc[h*132 + l + 32] = __uint_as_float(f2tf(w1));
        sc[h*132 + l + 64] = __uint_as_float(f2tf(w2));
        sc[h*132 + l + 96] = __uint_as_float(f2tf(w3));
        float sm = w0*mj[l] + w1*mj[l+32] + w2*mj[l+64] + w3*mj[l+96];
        #pragma unroll
        for (int o = 16; o > 0; o >>= 1) sm += __shfl_xor_sync(0xffffffffu, sm, o);
        if (l == 0) sh[h] = sm;
    }
    __syncthreads();

    // 7) ctx MMA + direct epilogue
    {
        int d0 = w * 16;
        float acc[4] = {0.f, 0.f, 0.f, 0.f};
        unsigned af[4];
        #pragma unroll
        for (int ks = 0; ks < 16; ks++) {
            int ko = ks * 8;
            af[0] = f2tf(zt[(ko+gc)*ZP   + d0 + gr]);
            af[1] = f2tf(zt[(ko+gc)*ZP   + d0 + gr + 8]);
            af[2] = f2tf(zt[(ko+gc+4)*ZP + d0 + gr]);
            af[3] = f2tf(zt[(ko+gc+4)*ZP + d0 + gr + 8]);
            unsigned b0 = __float_as_uint(sc[gr*132 + ko + gc]);
            unsigned b1 = __float_as_uint(sc[gr*132 + ko + gc + 4]);
            mma_tf32(acc, af, b0, b1);
        }
        int d = d0 + gr, d2 = d + 8;
        int h0 = 2*gc, h1 = h0 + 1;
        float s0 = sh[h0], s1 = sh[h1];
        float gzd = gz[d],  bzd = bz[d];
        float gz2 = gz[d2], bz2 = bz[d2];
        float* cb = &g_CTX[(size_t)bi*1024];
        cb[h0*128 + d]  = gzd*(acc[0] - s0) + bzd;
        cb[h1*128 + d]  = gzd*(acc[1] - s1) + bzd;
        cb[h0*128 + d2] = gz2*(acc[2] - s0) + bz2;
        cb[h1*128 + d2] = gz2*(acc[3] - s1) + bz2;
    }
}

// ---------------- launch ----------------
extern "C" void kernel_launch(void* const* d_in, const int* in_sizes, int n_in,
                              void* d_out, int out_size) {
    const float* z    = (const float*)d_in[0];
    const float* s    = (const float*)d_in[1];
    const int*   mask = (const int*)d_in[2];
    const float* wq   = (const float*)d_in[3];
    const float* bq   = (const float*)d_in[4];
    const float* wk   = (const float*)d_in[5];
    const float* bk   = (const float*)d_in[6];
    const float* wv   = (const float*)d_in[7];
    const float* bv   = (const float*)d_in[8];
    const float* wo   = (const float*)d_in[9];
    const float* bo   = (const float*)d_in[10];
    const float* gz   = (const float*)d_in[11];
    const float* bz   = (const float*)d_in[12];
    const float* gs   = (const float*)d_in[13];
    const float* bs   = (const float*)d_in[14];
    float* out = (float*)d_out;

    const int attn_smem = ATTN_SMEM_FLOATS * (int)sizeof(float);
    const int smem64    = (2*64*36 + 2*64*36) * (int)sizeof(float);
    const int smem6432  = (2*64*36 + 2*32*36) * (int)sizeof(float);
    const int smem3264  = (2*32*36 + 2*64*36) * (int)sizeof(float);
    cudaFuncSetAttribute(attn_kernel, cudaFuncAttributeMaxDynamicSharedMemorySize, attn_smem);
    cudaFuncSetAttribute(attn_kernel, cudaFuncAttributePreferredSharedMemoryCarveout, 100);
    cudaFuncSetAttribute(gemm_tc<64,64,2,4>, cudaFuncAttributeMaxDynamicSharedMemorySize, smem64);
    cudaFuncSetAttribute(gemm_tc<64,32,4,2>, cudaFuncAttributeMaxDynamicSharedMemorySize, smem6432);
    cudaFuncSetAttribute(gemm_tc<32,64,2,4>, cudaFuncAttributeMaxDynamicSharedMemorySize, smem3264);

    float *SN, *QKG, *CTX, *OUTS, *W3, *c3;
    cudaGetSymbolAddress((void**)&SN,   g_SN);
    cudaGetSymbolAddress((void**)&QKG,  g_QKG);
    cudaGetSymbolAddress((void**)&CTX,  g_CTX);
    cudaGetSymbolAddress((void**)&OUTS, g_OUTS);
    cudaGetSymbolAddress((void**)&W3,   g_W3);
    cudaGetSymbolAddress((void**)&c3,   g_c3);

    // launch idx:
    pre_kernel<<<BI + 1 + 128, 256>>>(s, gs, bs, wk, bk, bz, gz, wq, bq);                              // 0
    // QKG = SN @ W3^T + c3  [2048,1024] K=256
    gemm_tc<64,64,2,4><<<dim3(16,32), 256, smem64>>>(SN, DS, W3, DS, c3, QKG, Hh*DZ, DS, 1<<30, 0);    // 1
    attn_kernel<<<BI, 256, attn_smem>>>(z, mask, gz, bz);                                              // 2
    // OUTS = CTX(head) @ wv^T + bv  [2048,256] K=128
    gemm_tc<64,32,4,2><<<dim3(8,32), 256, smem6432>>>(CTX, Hh*DZ, wv, DZ, bv, OUTS, DS, DZ, HDIM, DZ); // 3
    // FINAL = OUTS @ wo^T + bo  [2048,256] K=256
    gemm_tc<32,64,2,4><<<dim3(4,64), 256, smem3264>>>(OUTS, DS, wo, DS, bo, out, DS, DS, 1<<30, 0);    // 4
}

// round 11
// speedup vs baseline: 1.1568x; 1.1568x over previous
#include <cuda_runtime.h>
#include <cstdint>
#include <math.h>

#define Bb 16
#define Nn 128
#define DZ 128
#define DS 256
#define Hh 8
#define HDIM 32
#define BI (Bb*Nn)
#define INV_SCALE 0.17677669529663687f
#define LN_EPS 1e-5f
#define ZP 132

// ---------------- scratch ----------------
__device__ __align__(16) float g_SN  [BI*DS];
__device__ __align__(16) float g_Q   [BI*DS];
__device__ __align__(16) float g_QKG [BI*Hh*DZ];
__device__ __align__(16) float g_CTX [BI*Hh*DZ];
__device__ __align__(16) float g_OUTS[BI*DS];
__device__ __align__(16) float g_wkb [DS];
__device__ __align__(16) float g_Wk2 [Hh*DZ*HDIM];   // [o=h*128+d][e]

__device__ __forceinline__ unsigned f2tf(float x) {
    unsigned r; asm("cvt.rna.tf32.f32 %0, %1;" : "=r"(r) : "f"(x)); return r;
}
__device__ __forceinline__ uint4 tf4(float4 v) {
    return make_uint4(f2tf(v.x), f2tf(v.y), f2tf(v.z), f2tf(v.w));
}
__device__ __forceinline__ void mma_tf32(float* c, const unsigned* a, unsigned b0, unsigned b1) {
    asm volatile(
        "mma.sync.aligned.m16n8k8.row.col.f32.tf32.tf32.f32 "
        "{%0,%1,%2,%3}, {%4,%5,%6,%7}, {%8,%9}, {%0,%1,%2,%3};"
        : "+f"(c[0]), "+f"(c[1]), "+f"(c[2]), "+f"(c[3])
        : "r"(a[0]), "r"(a[1]), "r"(a[2]), "r"(a[3]), "r"(b0), "r"(b1));
}
__device__ __forceinline__ void cp16(unsigned int dst, const void* src) {
    asm volatile("cp.async.cg.shared.global [%0], [%1], 16;\n" :: "r"(dst), "l"(src));
}

// ---------------- fused pre: s_query layernorm + weight prep ----------------
__global__ void pre_kernel(const float* __restrict__ s, const float* __restrict__ gs,
                           const float* __restrict__ bs,
                           const float* __restrict__ wk, const float* __restrict__ bk,
                           const float* __restrict__ bz, const float* __restrict__ gz) {
    int t = threadIdx.x;
    if (blockIdx.x < BI) {
        int bi = blockIdx.x;
        float x = s[(size_t)bi*DS + t];
        float sm = x, sq = x*x;
        #pragma unroll
        for (int o = 16; o > 0; o >>= 1) {
            sm += __shfl_xor_sync(0xffffffffu, sm, o);
            sq += __shfl_xor_sync(0xffffffffu, sq, o);
        }
        __shared__ float ps[8], pq[8], mv[2];
        int w = t >> 5, l = t & 31;
        if (l == 0) { ps[w] = sm; pq[w] = sq; }
        __syncthreads();
        if (t == 0) {
            float a = 0.f, b2 = 0.f;
            #pragma unroll
            for (int k = 0; k < 8; k++) { a += ps[k]; b2 += pq[k]; }
            float m = a * (1.0f/DS);
            mv[0] = m;
            mv[1] = rsqrtf(b2 * (1.0f/DS) - m*m + LN_EPS);
        }
        __syncthreads();
        g_SN[(size_t)bi*DS + t] = (x - mv[0]) * mv[1] * gs[t] + bs[t];
    } else {
        int pb = blockIdx.x - BI;
        int idx = pb * 256 + t;
        int o = idx >> 5, e = idx & 31;
        int h = o >> 7,  d = o & 127;
        g_Wk2[idx] = wk[(size_t)(h*HDIM + e)*DZ + d] * gz[d] * INV_SCALE;
        if (pb == 0) {
            int w = t >> 5, l = t & 31;
            for (int r = w; r < DS; r += 8) {
                float a = 0.f;
                #pragma unroll
                for (int k = 0; k < 4; k++) { int dd = l + 32*k; a += wk[(size_t)r*DZ + dd] * bz[dd]; }
                #pragma unroll
                for (int oo = 16; oo > 0; oo >>= 1) a += __shfl_xor_sync(0xffffffffu, a, oo);
                if (l == 0) g_wkb[r] = a + bk[r];
            }
        }
    }
}

// ---------------- tf32 GEMM ----------------
template<int BM, int BN, int WGM, int WGN>
__global__ __launch_bounds__(256) void gemm_tc(
        const float* __restrict__ A, int lda,
        const float* __restrict__ B, int ldb,
        const float* __restrict__ bias,
        float* __restrict__ C, int ldc, int K,
        int head_cols, int ahs) {
    constexpr int TM = BM/WGM, TN = BN/WGN, MF = TM/16, NF = TN/8;
    constexpr int LA = BM*8/256;
    constexpr int LB = BN*8/256;
    extern __shared__ float smem[];
    float* Asb = smem;
    float* Bsb = smem + 2*BM*36;

    int t = threadIdx.x, w = t >> 5, lane = t & 31;
    int gr = lane >> 2, gc = lane & 3;
    int wm = (w / WGN) * TM, wn = (w % WGN) * TN;
    int r0 = blockIdx.y * BM, c0 = blockIdx.x * BN;
    int abase = (c0 / head_cols) * ahs;

    float acc[MF][NF][4];
    #pragma unroll
    for (int mf = 0; mf < MF; mf++)
        #pragma unroll
        for (int nf = 0; nf < NF; nf++)
            #pragma unroll
            for (int q = 0; q < 4; q++) acc[mf][nf][q] = 0.f;

    float4 ra[LA], rb[LB];
    #pragma unroll
    for (int i = 0; i < LA; i++) {
        int idx = t + i*256; int row = idx >> 3, k4 = idx & 7;
        ra[i] = *reinterpret_cast<const float4*>(&A[(size_t)(r0+row)*lda + abase + k4*4]);
    }
    #pragma unroll
    for (int i = 0; i < LB; i++) {
        int idx = t + i*256; int row = idx >> 3, k4 = idx & 7;
        rb[i] = *reinterpret_cast<const float4*>(&B[(size_t)(c0+row)*ldb + k4*4]);
    }
    #pragma unroll
    for (int i = 0; i < LA; i++) {
        int idx = t + i*256; int row = idx >> 3, k4 = idx & 7;
        *reinterpret_cast<uint4*>(&Asb[row*36 + k4*4]) = tf4(ra[i]);
    }
    #pragma unroll
    for (int i = 0; i < LB; i++) {
        int idx = t + i*256; int row = idx >> 3, k4 = idx & 7;
        *reinterpret_cast<uint4*>(&Bsb[row*36 + k4*4]) = tf4(rb[i]);
    }
    __syncthreads();

    int nch = K >> 5;
    for (int ch = 0; ch < nch; ch++) {
        int cur = ch & 1;
        const float* As = Asb + cur*BM*36;
        const float* Bs = Bsb + cur*BN*36;
        if (ch + 1 < nch) {
            int kc = (ch+1)*32;
            #pragma unroll
            for (int i = 0; i < LA; i++) {
                int idx = t + i*256; int row = idx >> 3, k4 = idx & 7;
                ra[i] = *reinterpret_cast<const float4*>(&A[(size_t)(r0+row)*lda + abase + kc + k4*4]);
            }
            #pragma unroll
            for (int i = 0; i < LB; i++) {
                int idx = t + i*256; int row = idx >> 3, k4 = idx & 7;
                rb[i] = *reinterpret_cast<const float4*>(&B[(size_t)(c0+row)*ldb + kc + k4*4]);
            }
        }
        #pragma unroll
        for (int ks = 0; ks < 4; ks++) {
            int ko = ks * 8;
            unsigned af[MF][4];
            #pragma unroll
            for (int mf = 0; mf < MF; mf++) {
                const float* ap = &As[(wm + mf*16 + gr)*36 + ko + gc];
                af[mf][0] = __float_as_uint(ap[0]);
                af[mf][1] = __float_as_uint(ap[8*36]);
                af[mf][2] = __float_as_uint(ap[4]);
                af[mf][3] = __float_as_uint(ap[8*36 + 4]);
            }
            #pragma unroll
            for (int nf = 0; nf < NF; nf++) {
                const float* bp = &Bs[(wn + nf*8 + gr)*36 + ko + gc];
                unsigned b0 = __float_as_uint(bp[0]), b1 = __float_as_uint(bp[4]);
                #pragma unroll
                for (int mf = 0; mf < MF; mf++)
                    mma_tf32(acc[mf][nf], af[mf], b0, b1);
            }
        }
        if (ch + 1 < nch) {
            int nxt = cur ^ 1;
            float* Asn = Asb + nxt*BM*36;
            float* Bsn = Bsb + nxt*BN*36;
            #pragma unroll
            for (int i = 0; i < LA; i++) {
                int idx = t + i*256; int row = idx >> 3, k4 = idx & 7;
                *reinterpret_cast<uint4*>(&Asn[row*36 + k4*4]) = tf4(ra[i]);
            }
            #pragma unroll
            for (int i = 0; i < LB; i++) {
                int idx = t + i*256; int row = idx >> 3, k4 = idx & 7;
                *reinterpret_cast<uint4*>(&Bsn[row*36 + k4*4]) = tf4(rb[i]);
            }
            __syncthreads();
        }
    }

    #pragma unroll
    for (int mf = 0; mf < MF; mf++) {
        #pragma unroll
        for (int nf = 0; nf < NF; nf++) {
            int row = r0 + wm + mf*16 + gr;
            int col = c0 + wn + nf*8 + 2*gc;
            float bx = 0.f, by = 0.f;
            if (bias) { bx = bias[col]; by = bias[col+1]; }
            float2 v0 = make_float2(acc[mf][nf][0] + bx, acc[mf][nf][1] + by);
            float2 v1 = make_float2(acc[mf][nf][2] + bx, acc[mf][nf][3] + by);
            *reinterpret_cast<float2*>(&C[(size_t)row*ldc + col])     = v0;
            *reinterpret_cast<float2*>(&C[(size_t)(row+8)*ldc + col]) = v1;
        }
    }
}

// ---------------- fused edge-LN + attention (warp-private z rows, 3 CTA/SM) ----------------
// smem: zt[128*132] (mj/rj live in cols 128/129 of each row) | qa[8*132] | sc[8*132] | Ah[8] cqh[8] sh[8]
#define ATTN_SMEM_FLOATS (128*ZP + 2*8*132 + 24)
#define MJ(j) zt[(j)*ZP + 128]
#define RJ(j) zt[(j)*ZP + 129]

__global__ __launch_bounds__(256) void attn_kernel(
        const float* __restrict__ z, const int* __restrict__ mask,
        const float* __restrict__ gz, const float* __restrict__ bz) {
    extern __shared__ float smem[];
    float* zt  = smem;                 // raw fp32 z tile (+LN stats in padding)
    float* qa  = zt  + 128*ZP;         // tf32 qkg
    float* sc  = qa  + 8*132;          // scores -> tf32 weights
    float* Ah  = sc  + 8*132;
    float* cqh = Ah  + 8;
    float* sh  = cqh + 8;

    int bi = blockIdx.x, b = bi >> 7;
    int t = threadIdx.x, w = t >> 5, l = t & 31;
    int gr = l >> 2, gc = l & 3;
    int j0 = w * 16;

    // 1) warp-private z copies: warp w copies rows [16w, 16w+16)
    {
        unsigned int zt_base = (unsigned int)__cvta_generic_to_shared(zt);
        const float* zb = z + (size_t)bi * 16384;
        #pragma unroll
        for (int k = 0; k < 16; k++) {
            int row = j0 + k;
            cp16(zt_base + (unsigned int)((row*ZP + l*4)*4), zb + row*128 + l*4);
        }
        asm volatile("cp.async.commit_group;\n");
    }

    // 2) overlap: qa (tf32) + Ah; cq fold from Q . wkb
    {
        float4 v = *reinterpret_cast<const float4*>(&g_QKG[(size_t)bi*1024 + w*128 + l*4]);
        uint4 tv = tf4(v);
        *reinterpret_cast<uint4*>(&qa[w*132 + l*4]) = tv;
        float s = __uint_as_float(tv.x) + __uint_as_float(tv.y)
                + __uint_as_float(tv.z) + __uint_as_float(tv.w);
        #pragma unroll
        for (int o = 16; o > 0; o >>= 1) s += __shfl_xor_sync(0xffffffffu, s, o);
        if (l == 0) Ah[w] = s;
    }
    {
        float a = g_Q[(size_t)bi*DS + w*HDIM + l] * g_wkb[w*HDIM + l];
        #pragma unroll
        for (int o = 16; o > 0; o >>= 1) a += __shfl_xor_sync(0xffffffffu, a, o);
        if (l == 0) cqh[w] = a * INV_SCALE;
    }
    __syncthreads();   // publish qa/Ah/cqh

    // 3) wait own z rows only (warp-local)
    asm volatile("cp.async.wait_group 0;\n");
    __syncwarp();

    // 4) LN stats for own rows: lane pair per row -> stats into zt row padding
    {
        int jr = j0 + (l >> 1);
        const float* rp = &zt[jr*ZP + (l & 1)*64];
        float s = 0.f, sq = 0.f;
        #pragma unroll
        for (int k = 0; k < 16; k++) {
            float4 v = *reinterpret_cast<const float4*>(rp + 4*k);
            s  += v.x + v.y + v.z + v.w;
            sq += v.x*v.x + v.y*v.y + v.z*v.z + v.w*v.w;
        }
        s  += __shfl_xor_sync(0xffffffffu, s,  1);
        sq += __shfl_xor_sync(0xffffffffu, sq, 1);
        if ((l & 1) == 0) {
            float m = s * (1.0f/128.0f);
            MJ(jr) = m;
            RJ(jr) = rsqrtf(sq * (1.0f/128.0f) - m*m + LN_EPS);
        }
    }
    __syncwarp();

    // 5) scores MMA for own rows
    {
        float acc[4] = {0.f, 0.f, 0.f, 0.f};
        unsigned af[4];
        #pragma unroll
        for (int ks = 0; ks < 16; ks++) {
            int ko = ks * 8;
            af[0] = f2tf(zt[(j0+gr)*ZP   + ko + gc]);
            af[1] = f2tf(zt[(j0+gr+8)*ZP + ko + gc]);
            af[2] = f2tf(zt[(j0+gr)*ZP   + ko + gc + 4]);
            af[3] = f2tf(zt[(j0+gr+8)*ZP + ko + gc + 4]);
            unsigned b0 = __float_as_uint(qa[gr*132 + ko + gc]);
            unsigned b1 = __float_as_uint(qa[gr*132 + ko + gc + 4]);
            mma_tf32(acc, af, b0, b1);
        }
        int jA = j0 + gr, jB = j0 + gr + 8;
        int h0 = 2*gc, h1 = 2*gc + 1;
        const int* mrow = &mask[b*128];
        float aA = (mrow[jA] != 0) ? 0.f : -3.0e38f;
        float aB = (mrow[jB] != 0) ? 0.f : -3.0e38f;
        float rA = RJ(jA), mA = MJ(jA);
        float rB = RJ(jB), mB = MJ(jB);
        float A0 = Ah[h0], A1 = Ah[h1], C0 = cqh[h0], C1 = cqh[h1];
        sc[h0*132 + jA] = rA*(acc[0] - mA*A0) + C0 + aA;
        sc[h1*132 + jA] = rA*(acc[1] - mA*A1) + C1 + aA;
        sc[h0*132 + jB] = rB*(acc[2] - mB*A0) + C0 + aB;
        sc[h1*132 + jB] = rB*(acc[3] - mB*A1) + C1 + aB;
    }
    __syncthreads();

    // 6) softmax per head; sc becomes aw = attn*r (tf32); sh[h] = sum_j aw*m
    {
        int h = w;
        float v0 = sc[h*132 + l],      v1 = sc[h*132 + l + 32];
        float v2 = sc[h*132 + l + 64], v3 = sc[h*132 + l + 96];
        float mx = fmaxf(fmaxf(v0, v1), fmaxf(v2, v3));
        #pragma unroll
        for (int o = 16; o > 0; o >>= 1) mx = fmaxf(mx, __shfl_xor_sync(0xffffffffu, mx, o));
        float e0 = expf(v0-mx), e1 = expf(v1-mx), e2 = expf(v2-mx), e3 = expf(v3-mx);
        float s = e0+e1+e2+e3;
        #pragma unroll
        for (int o = 16; o > 0; o >>= 1) s += __shfl_xor_sync(0xffffffffu, s, o);
        float inv = 1.0f / s;
        float w0 = e0*inv*RJ(l),    w1 = e1*inv*RJ(l+32);
        float w2 = e2*inv*RJ(l+64), w3 = e3*inv*RJ(l+96);
        sc[h*132 + l]      = __uint_as_float(f2tf(w0));
        sc[h*132 + l + 32] = __uint_as_float(f2tf(w1));
        sc[h*132 + l + 64] = __uint_as_float(f2tf(w2));
        sc[h*132 + l + 96] = __uint_as_float(f2tf(w3));
        float sm = w0*MJ(l) + w1*MJ(l+32) + w2*MJ(l+64) + w3*MJ(l+96);
        #pragma unroll
        for (int o = 16; o > 0; o >>= 1) sm += __shfl_xor_sync(0xffffffffu, sm, o);
        if (l == 0) sh[h] = sm;
    }
    __syncthreads();

    // 7) ctx MMA + direct epilogue
    {
        int d0 = w * 16;
        float acc[4] = {0.f, 0.f, 0.f, 0.f};
        unsigned af[4];
        #pragma unroll
        for (int ks = 0; ks < 16; ks++) {
            int ko = ks * 8;
            af[0] = f2tf(zt[(ko+gc)*ZP   + d0 + gr]);
            af[1] = f2tf(zt[(ko+gc)*ZP   + d0 + gr + 8]);
            af[2] = f2tf(zt[(ko+gc+4)*ZP + d0 + gr]);
            af[3] = f2tf(zt[(ko+gc+4)*ZP + d0 + gr + 8]);
            unsigned b0 = __float_as_uint(sc[gr*132 + ko + gc]);
            unsigned b1 = __float_as_uint(sc[gr*132 + ko + gc + 4]);
            mma_tf32(acc, af, b0, b1);
        }
        int d = d0 + gr, d2 = d + 8;
        int h0 = 2*gc, h1 = h0 + 1;
        float s0 = sh[h0], s1 = sh[h1];
        float gzd = gz[d],  bzd = bz[d];
        float gz2 = gz[d2], bz2 = bz[d2];
        float* cb = &g_CTX[(size_t)bi*1024];
        cb[h0*128 + d]  = gzd*(acc[0] - s0) + bzd;
        cb[h1*128 + d]  = gzd*(acc[1] - s1) + bzd;
        cb[h0*128 + d2] = gz2*(acc[2] - s0) + bz2;
        cb[h1*128 + d2] = gz2*(acc[3] - s1) + bz2;
    }
}

// ---------------- launch ----------------
extern "C" void kernel_launch(void* const* d_in, const int* in_sizes, int n_in,
                              void* d_out, int out_size) {
    const float* z    = (const float*)d_in[0];
    const float* s    = (const float*)d_in[1];
    const int*   mask = (const int*)d_in[2];
    const float* wq   = (const float*)d_in[3];
    const float* bq   = (const float*)d_in[4];
    const float* wk   = (const float*)d_in[5];
    const float* bk   = (const float*)d_in[6];
    const float* wv   = (const float*)d_in[7];
    const float* bv   = (const float*)d_in[8];
    const float* wo   = (const float*)d_in[9];
    const float* bo   = (const float*)d_in[10];
    const float* gz   = (const float*)d_in[11];
    const float* bz   = (const float*)d_in[12];
    const float* gs   = (const float*)d_in[13];
    const float* bs   = (const float*)d_in[14];
    float* out = (float*)d_out;

    const int attn_smem = ATTN_SMEM_FLOATS * (int)sizeof(float);   // 76128 B
    const int smem64    = (2*64*36 + 2*64*36) * (int)sizeof(float);
    const int smem6432  = (2*64*36 + 2*32*36) * (int)sizeof(float);
    const int smem3264  = (2*32*36 + 2*64*36) * (int)sizeof(float);
    cudaFuncSetAttribute(attn_kernel, cudaFuncAttributeMaxDynamicSharedMemorySize, attn_smem);
    cudaFuncSetAttribute(attn_kernel, cudaFuncAttributePreferredSharedMemoryCarveout, 100);
    cudaFuncSetAttribute(gemm_tc<64,64,2,4>, cudaFuncAttributeMaxDynamicSharedMemorySize, smem64);
    cudaFuncSetAttribute(gemm_tc<64,32,4,2>, cudaFuncAttributeMaxDynamicSharedMemorySize, smem6432);
    cudaFuncSetAttribute(gemm_tc<32,64,2,4>, cudaFuncAttributeMaxDynamicSharedMemorySize, smem3264);

    float *SN, *Q, *QKG, *CTX, *OUTS, *Wk2;
    cudaGetSymbolAddress((void**)&SN,   g_SN);
    cudaGetSymbolAddress((void**)&Q,    g_Q);
    cudaGetSymbolAddress((void**)&QKG,  g_QKG);
    cudaGetSymbolAddress((void**)&CTX,  g_CTX);
    cudaGetSymbolAddress((void**)&OUTS, g_OUTS);
    cudaGetSymbolAddress((void**)&Wk2,  g_Wk2);

    // launch idx:
    pre_kernel<<<BI + 128, 256>>>(s, gs, bs, wk, bk, bz, gz);                                          // 0
    gemm_tc<32,64,2,4><<<dim3(4,64), 256, smem3264>>>(SN, DS, wq, DS, bq, Q, DS, DS, 1<<30, 0);        // 1
    gemm_tc<64,64,2,4><<<dim3(16,32), 256, smem64>>>(Q, DS, Wk2, HDIM, nullptr, QKG, Hh*DZ, HDIM, DZ, HDIM); // 2
    attn_kernel<<<BI, 256, attn_smem>>>(z, mask, gz, bz);                                              // 3  <- profiled
    gemm_tc<64,32,4,2><<<dim3(8,32), 256, smem6432>>>(CTX, Hh*DZ, wv, DZ, bv, OUTS, DS, DZ, HDIM, DZ); // 4
    gemm_tc<32,64,2,4><<<dim3(4,64), 256, smem3264>>>(OUTS, DS, wo, DS, bo, out, DS, DS, 1<<30, 0);    // 5
}